// round 15
// baseline (speedup 1.0000x reference)
#include <cuda_runtime.h>
#include <cuda_fp16.h>
#include <stdint.h>

// ---------------- problem constants ----------------
#define T_    4
#define B_    2
#define NW    64
#define WS    128
#define C_    256
#define H_    8
#define TOPK  4
#define NGRP  512        // T*B*NW
#define MROWS 65536      // NGRP*WS
#define MARGIN0 1.0e-2f  // qkv margin: fp16 inputs + fp16 accum (~8.7 sigma)

// ---------------- device scratch ----------------
__device__ float    g_rpart[128*8*C_];
__device__ float    g_region[B_*NW*C_];
__device__ int      g_idx[B_*NW*TOPK];
__device__ unsigned g_qb[NGRP*H_*WS];
__device__ unsigned g_kb[NGRP*H_*WS];
__device__ unsigned g_vb[NGRP*H_*WS];
__device__ unsigned g_kt[NGRP*H_*4*32];
__device__ unsigned g_vt[NGRP*H_*4*32];
__device__ __half   g_xh[(size_t)MROWS*C_];   // gathered x, fp16
__device__ __half   g_ah[(size_t)MROWS*C_];   // attention out, fp16
__device__ __half   g_Wq_h[768*256];          // [n][k] fp16
__device__ __half   g_Wp_h[256*256];
__device__ float    g_Wqt[768*256];           // fp32 transposed Wqkv [n][k] (refine)

// row (grp, s) -> float offset of x[t,b,lt,lh,lw,0]
__device__ __forceinline__ int x_row_off(int grp, int s) {
    int n  = grp & 63;
    int tb = grp >> 6;
    int iwt = n >> 4, iwh = (n >> 2) & 3, iww = n & 3;
    int ipt = s >> 6, iph = (s >> 3) & 7, ipw = s & 7;
    int lt = iwt*2 + ipt;
    int lh = iwh*8 + iph;
    int lw = iww*8 + ipw;
    return (((tb*8 + lt)*32 + lh)*32 + lw) * C_;
}

__device__ __forceinline__ uint32_t smem_to_u32(const void* p) {
    uint32_t a;
    asm("{ .reg .u64 t; cvta.to.shared.u64 t, %1; cvt.u32.u64 %0, t; }" : "=r"(a) : "l"(p));
    return a;
}
__device__ __forceinline__ void cp16(uint32_t dst, const void* src) {
    asm volatile("cp.async.cg.shared.global [%0], [%1], 16;" :: "r"(dst), "l"(src));
}
__device__ __forceinline__ void mma16816(float* c, const uint32_t* a, const uint32_t* b) {
    asm volatile(
        "mma.sync.aligned.m16n8k16.row.col.f32.f16.f16.f32 "
        "{%0,%1,%2,%3}, {%4,%5,%6,%7}, {%8,%9}, {%0,%1,%2,%3};"
        : "+f"(c[0]), "+f"(c[1]), "+f"(c[2]), "+f"(c[3])
        : "r"(a[0]), "r"(a[1]), "r"(a[2]), "r"(a[3]), "r"(b[0]), "r"(b[1]));
}
__device__ __forceinline__ void mma16816h(uint32_t* c, const uint32_t* a, const uint32_t* b) {
    asm volatile(
        "mma.sync.aligned.m16n8k16.row.col.f16.f16.f16.f16 "
        "{%0,%1}, {%2,%3,%4,%5}, {%6,%7}, {%0,%1};"
        : "+r"(c[0]), "+r"(c[1])
        : "r"(a[0]), "r"(a[1]), "r"(a[2]), "r"(a[3]), "r"(b[0]), "r"(b[1]));
}

// fp32 sequential-fma recompute in reference-matching order; coalesced W.
__device__ float refine_dot(const float* __restrict__ x, int by, int s, int col) {
    const float* xr = x + x_row_off(by, s);
    const float* wc = g_Wqt + (size_t)col * 256;
    float acc = 0.f;
    for (int k = 0; k < 256; k++)
        acc = fmaf(xr[k], wc[k], acc);
    return acc;
}

// ---------------- K1: fused windowize-gather(fp16) + region partials ----------------
__global__ void gather_region_kernel(const float* __restrict__ x) {
    int bn = blockIdx.x, ch = blockIdx.y, c = threadIdx.x;
    int b = bn >> 6, n = bn & 63;
    float acc = 0.f;
    #pragma unroll 4
    for (int l = 0; l < 64; l++) {
        int p = ch*64 + l;
        int t = p >> 7, s = p & 127;
        int grp = (t*B_ + b)*NW + n;
        float v = x[x_row_off(grp, s) + c];
        acc += v;
        g_xh[(size_t)(grp*WS + s)*C_ + c] = __float2half_rn(v);
    }
    g_rpart[(bn*8 + ch)*C_ + c] = acc;
}

// ---------------- K2: W transpose + fp16 cast ----------------
__global__ void wtrans_kernel(const float* __restrict__ Wqkv,
                              const float* __restrict__ Wproj) {
    int idx = blockIdx.x*256 + threadIdx.x;
    if (idx < 256*768) {
        int k = idx / 768, n = idx % 768;
        float v = Wqkv[idx];
        g_Wq_h[n*256 + k] = __float2half_rn(v);
        g_Wqt[(size_t)n*256 + k] = v;
    }
    if (idx < 256*256) {
        int k = idx / 256, n = idx % 256;
        g_Wp_h[n*256 + k] = __float2half_rn(Wproj[idx]);
    }
}

// ---------------- K3: region final reduce ----------------
__global__ void region_b_kernel() {
    int bn = blockIdx.x, c = threadIdx.x;
    float acc = 0.f;
    #pragma unroll
    for (int ch = 0; ch < 8; ch++) acc += g_rpart[(bn*8 + ch)*C_ + c];
    g_region[bn*C_ + c] = acc * (1.0f / WS);
}

// ---------------- K5: routing top-4 (parallel dots) ----------------
__global__ void route_kernel() {
    int bi = blockIdx.x;
    int b  = bi >> 6;
    __shared__ float sI[C_];
    __shared__ float sc[NW];
    sI[threadIdx.x] = g_region[bi*C_ + threadIdx.x];   // 256 threads
    __syncthreads();
    int j = threadIdx.x >> 2, q = threadIdx.x & 3;
    const float* rj = &g_region[(b*NW + j)*C_];
    float d = 0.f;
    #pragma unroll 8
    for (int c = q*64; c < q*64 + 64; c++) d += sI[c] * rj[c];
    d += __shfl_xor_sync(0xffffffffu, d, 1);
    d += __shfl_xor_sync(0xffffffffu, d, 2);
    if (q == 0) sc[j] = d;
    __syncthreads();
    if (threadIdx.x == 0) {
        unsigned long long taken = 0ull;
        for (int r = 0; r < TOPK; r++) {
            float best = -1e30f; int bj = 0;
            for (int jj = 0; jj < NW; jj++)
                if (!((taken >> jj) & 1ull) && sc[jj] > best) { best = sc[jj]; bj = jj; }
            taken |= 1ull << bj;
            g_idx[bi*TOPK + r] = bj;
        }
    }
}

// ---------------- K4/K8: 1-pass fp16 GEMM via mma.sync ----------------
// CTA tile 128x128, 8 warps (2x4, warp 64x32), BK=32, XOR-swizzled 64B rows,
// 3-stage cp.async, 2 CTAs/SM.
// MODE 0: fp16-accum HMMA; A = g_xh, B = Wqkv; epi = LIF + margin-refine + bitpack
// MODE 1: fp32-accum HMMA; A = g_ah, B = Wproj; epi = bias + un-windowize
#define A_PANE  8192               // 128 rows * 64 B
#define STB     16384              // A + B per stage
#define NSTAGE  3                  // 48 KB total (static smem cap)
#define SWZ(row, p) (((p) ^ (((row) >> 1) & 3)) * 16)

template<int MODE>
__global__ void __launch_bounds__(256, 2)
gemm_mma_kernel(const float* __restrict__ bias_g, float* __restrict__ out,
                const float* __restrict__ x_full) {
    __shared__ __align__(16) char smem[NSTAGE*STB];    // 49152 = 48 KB
    uint32_t sb = smem_to_u32(smem);
    int tid = threadIdx.x, lane = tid & 31, wid = tid >> 5;
    int warp_m = wid & 1, warp_n = wid >> 1;           // 2 x 4 (warp 64x32)
    int bx = blockIdx.x, by = blockIdx.y;

    const __half* Ah = (MODE == 0) ? g_xh : g_ah;
    const __half* Bh = (MODE == 0) ? g_Wq_h : g_Wp_h;
    size_t arow0 = (size_t)by * 128 * 256;
    size_t brow0 = (size_t)bx * 128 * 256;

    float bv[4][2];
    #pragma unroll
    for (int ni = 0; ni < 4; ni++) {
        int col = bx*128 + warp_n*32 + ni*8 + 2*(lane & 3);
        bv[ni][0] = bias_g[col];
        bv[ni][1] = bias_g[col + 1];
    }

    // loads: per stage, each thread does 2 A + 2 B 16B chunks
    auto stage_load = [&](int c, int s) {
        uint32_t base = sb + s*STB;
        #pragma unroll
        for (int i = 0; i < 2; i++) {
            int idx = i*256 + tid;              // 0..511
            int row = idx >> 2, p = idx & 3;    // row 0..127, 16B part 0..3
            uint32_t doff = row*64 + SWZ(row, p);
            cp16(base + doff,          Ah + arow0 + (size_t)row*256 + c*32 + p*8);
            cp16(base + A_PANE + doff, Bh + brow0 + (size_t)row*256 + c*32 + p*8);
        }
        asm volatile("cp.async.commit_group;" ::: "memory");
    };

    float    cf[MODE == 1 ? 4 : 1][4][4];      // fp32 accum (MODE 1)
    uint32_t hf[MODE == 0 ? 4 : 1][4][2];      // fp16 accum (MODE 0), half2 packed
    if (MODE == 1) {
        #pragma unroll
        for (int i = 0; i < 4; i++)
            #pragma unroll
            for (int j = 0; j < 4; j++)
                #pragma unroll
                for (int k = 0; k < 4; k++) cf[i][j][k] = 0.f;
    } else {
        #pragma unroll
        for (int i = 0; i < 4; i++)
            #pragma unroll
            for (int j = 0; j < 4; j++) { hf[i][j][0] = 0u; hf[i][j][1] = 0u; }
    }

    stage_load(0, 0);
    stage_load(1, 1);
    int sc_ = 0;
    for (int ch = 0; ch < 8; ch++) {       // 8 chunks of K=32
        if (ch < 7) {
            asm volatile("cp.async.wait_group 1;" ::: "memory");
        } else {
            asm volatile("cp.async.wait_group 0;" ::: "memory");
        }
        __syncthreads();
        if (ch < 6) {
            int s2 = sc_ + 2; if (s2 >= NSTAGE) s2 -= NSTAGE;
            stage_load(ch + 2, s2);
        }
        uint32_t stb = sb + sc_*STB;

        #pragma unroll
        for (int ks = 0; ks < 2; ks++) {   // two k16 steps within chunk
            uint32_t bh[4][2];
            #pragma unroll
            for (int ni = 0; ni < 4; ni++) {
                int n = warp_n*32 + ni*8 + (lane & 7);
                int p = 2*ks + ((lane >> 3) & 1);
                asm volatile("ldmatrix.sync.aligned.m8n8.x2.shared.b16 {%0,%1}, [%2];"
                    : "=r"(bh[ni][0]), "=r"(bh[ni][1])
                    : "r"(stb + A_PANE + n*64 + SWZ(n, p)));
            }
            #pragma unroll
            for (int mi = 0; mi < 4; mi++) {
                int m = warp_m*64 + mi*16 + (lane & 15);
                int p = 2*ks + (lane >> 4);
                uint32_t ah_[4];
                asm volatile("ldmatrix.sync.aligned.m8n8.x4.shared.b16 {%0,%1,%2,%3}, [%4];"
                    : "=r"(ah_[0]), "=r"(ah_[1]), "=r"(ah_[2]), "=r"(ah_[3])
                    : "r"(stb + m*64 + SWZ(m, p)));
                #pragma unroll
                for (int ni = 0; ni < 4; ni++) {
                    if (MODE == 0) mma16816h(hf[mi][ni], ah_, bh[ni]);
                    else           mma16816(cf[mi][ni], ah_, bh[ni]);
                }
            }
        }
        if (++sc_ >= NSTAGE) sc_ = 0;
    }

    // ---------------- epilogue ----------------
    if (MODE == 0) {
        #pragma unroll
        for (int mi = 0; mi < 4; mi++) {
            #pragma unroll
            for (int half = 0; half < 2; half++) {
                int s = warp_m*64 + mi*16 + half*8 + (lane >> 2);
                unsigned w = 0;
                #pragma unroll
                for (int ni = 0; ni < 4; ni++) {
                    int col = bx*128 + warp_n*32 + ni*8 + 2*(lane & 3);
                    __half2 p2 = *reinterpret_cast<__half2*>(&hf[mi][ni][half]);
                    float v0 = __low2float(p2)  + bv[ni][0];
                    float v1 = __high2float(p2) + bv[ni][1];
                    if (fabsf(v0 - 2.0f) < MARGIN0)
                        v0 = refine_dot(x_full, by, s, col) + bv[ni][0];
                    if (fabsf(v1 - 2.0f) < MARGIN0)
                        v1 = refine_dot(x_full, by, s, col + 1) + bv[ni][1];
                    int sh = ni*8 + 2*(lane & 3);
                    w |= (v0 >= 2.0f ? 1u : 0u) << sh;
                    w |= (v1 >= 2.0f ? 1u : 0u) << (sh + 1);
                }
                w |= __shfl_xor_sync(0xffffffffu, w, 1);
                w |= __shfl_xor_sync(0xffffffffu, w, 2);
                if ((lane & 3) == 0) {
                    int wcol = bx*4 + warp_n;          // 0..23
                    unsigned* dst = (wcol < 8) ? g_qb : ((wcol < 16) ? g_kb : g_vb);
                    dst[(by*H_ + (wcol & 7))*WS + s] = w;
                }
            }
        }
    } else {
        #pragma unroll
        for (int mi = 0; mi < 4; mi++) {
            #pragma unroll
            for (int half = 0; half < 2; half++) {
                int s = warp_m*64 + mi*16 + half*8 + (lane >> 2);
                int xo = x_row_off(by, s) + bx*128 + warp_n*32;
                #pragma unroll
                for (int ni = 0; ni < 4; ni++) {
                    float2 o;
                    o.x = cf[mi][ni][half*2 + 0] + bv[ni][0];
                    o.y = cf[mi][ni][half*2 + 1] + bv[ni][1];
                    *(float2*)&out[xo + ni*8 + 2*(lane & 3)] = o;
                }
            }
        }
    }
}

// ---------------- K6: per-window bit transpose ----------------
__global__ void transpose_kernel() {
    int grp = blockIdx.x;
    int wid = threadIdx.x >> 5, lane = threadIdx.x & 31;
    int base = (grp*H_ + wid);
    #pragma unroll
    for (int cc = 0; cc < 4; cc++) {
        unsigned kw = g_kb[base*WS + cc*32 + lane];
        unsigned vw = g_vb[base*WS + cc*32 + lane];
        unsigned kt = 0, vt = 0;
        #pragma unroll
        for (int d = 0; d < 32; d++) {
            unsigned mk = __ballot_sync(0xffffffffu, (kw >> d) & 1u);
            unsigned mv = __ballot_sync(0xffffffffu, (vw >> d) & 1u);
            if (lane == d) { kt = mk; vt = mv; }
        }
        g_kt[(base*4 + cc)*32 + lane] = kt;
        g_vt[(base*4 + cc)*32 + lane] = vt;
    }
}

// ---------------- K7: popcount linear attention, sparse-q output ----------------
__global__ void __launch_bounds__(256) attn_kernel() {
    int grp = blockIdx.x;
    int n = grp & 63, tb = grp >> 6, b = tb % B_;
    int wid = threadIdx.x >> 5, lane = threadIdx.x & 31;
    int h = wid;
    __shared__ int s_idx[TOPK];
    __shared__ int s_ks[H_][32];
    __shared__ int s_kv[H_][32][32];   // [h][d][e]
    if (threadIdx.x < TOPK)
        s_idx[threadIdx.x] = g_idx[(b*NW + n)*TOPK + threadIdx.x];
    __syncthreads();

    unsigned kv[32];
    #pragma unroll
    for (int d = 0; d < 32; d++) kv[d] = 0;
    unsigned ksum = 0;

    for (int j = 0; j < TOPK; j++) {
        int gsrc = tb*NW + s_idx[j];
        const unsigned* ktp = &g_kt[(gsrc*H_ + h)*4*32];
        const unsigned* vtp = &g_vt[(gsrc*H_ + h)*4*32];
        #pragma unroll
        for (int cc = 0; cc < 4; cc++) {
            unsigned ktw = ktp[cc*32 + lane];
            unsigned vtw = vtp[cc*32 + lane];
            ksum += __popc(ktw);
            #pragma unroll
            for (int d = 0; d < 32; d++) {
                unsigned km = __shfl_sync(0xffffffffu, ktw, d);
                kv[d] += __popc(km & vtw);
            }
        }
    }
    #pragma unroll
    for (int d = 0; d < 32; d++) s_kv[h][d][lane] = (int)kv[d];
    s_ks[h][lane] = (int)ksum;
    __syncwarp();

    const int* kvh = &s_kv[h][0][0];
    const int* ksh = &s_ks[h][0];
    const unsigned* qp = &g_qb[(grp*H_ + h)*WS];
    for (int cc = 0; cc < 4; cc++) {
        unsigned qwl = qp[cc*32 + lane];
        #pragma unroll 4
        for (int i = 0; i < 32; i++) {
            unsigned qw = __shfl_sync(0xffffffffu, qwl, i);
            float o = 0.f;
            if (qw) {                          // uniform branch
                int acc = 0, Dv = 0;
                unsigned m = qw;
                do {
                    int d = __ffs(m) - 1;
                    m &= m - 1;
                    acc += kvh[d*32 + lane];
                    Dv  += ksh[d];
                } while (m);
                o = (float)acc / ((float)Dv + 1e-6f);
            }
            size_t off = ((size_t)(grp*WS + cc*32 + i))*C_ + h*32 + lane;
            g_ah[off] = __float2half_rn(o);
        }
    }
}

// ---------------- launcher ----------------
extern "C" void kernel_launch(void* const* d_in, const int* in_sizes, int n_in,
                              void* d_out, int out_size) {
    const float* x      = (const float*)d_in[0];
    const float* W_qkv  = (const float*)d_in[1];
    const float* b_qkv  = (const float*)d_in[2];
    const float* W_proj = (const float*)d_in[3];
    const float* b_proj = (const float*)d_in[4];
    float* out = (float*)d_out;

    gather_region_kernel<<<dim3(128, 8), 256>>>(x);   // 1
    wtrans_kernel<<<768, 256>>>(W_qkv, W_proj);       // 2
    region_b_kernel<<<128, 256>>>();                  // 3
    gemm_mma_kernel<0><<<dim3(6, NGRP), 256>>>(b_qkv, nullptr, x);  // 4 <- ncu slot
    route_kernel<<<B_*NW, 256>>>();                   // 5
    transpose_kernel<<<NGRP, 256>>>();                // 6
    attn_kernel<<<NGRP, 256>>>();                     // 7
    gemm_mma_kernel<1><<<dim3(2, NGRP), 256>>>(b_proj, out, nullptr);  // 8
}

// round 16
// speedup vs baseline: 1.5058x; 1.5058x over previous
#include <cuda_runtime.h>
#include <cuda_fp16.h>
#include <stdint.h>

// ---------------- problem constants ----------------
#define T_    4
#define B_    2
#define NW    64
#define WS    128
#define C_    256
#define H_    8
#define TOPK  4
#define NGRP  512        // T*B*NW
#define MROWS 65536      // NGRP*WS
#define MARGIN0 2.5e-3f  // qkv 1-pass fp16 margin (~12.5 sigma)

// ---------------- device scratch ----------------
__device__ float    g_rpart[128*8*C_];
__device__ float    g_region[B_*NW*C_];
__device__ int      g_idx[B_*NW*TOPK];
__device__ unsigned g_qb[NGRP*H_*WS];
__device__ unsigned g_kb[NGRP*H_*WS];
__device__ unsigned g_vb[NGRP*H_*WS];
__device__ unsigned g_kt[NGRP*H_*4*32];
__device__ unsigned g_vt[NGRP*H_*4*32];
__device__ __half   g_xh[(size_t)MROWS*C_];   // gathered x, fp16
__device__ __half   g_ah[(size_t)MROWS*C_];   // attention out, fp16
__device__ __half   g_Wq_h[768*256];          // [n][k] fp16
__device__ __half   g_Wp_h[256*256];
__device__ float    g_Wqt[768*256];           // fp32 transposed Wqkv [n][k] (refine)

// row (grp, s) -> float offset of x[t,b,lt,lh,lw,0]
__device__ __forceinline__ int x_row_off(int grp, int s) {
    int n  = grp & 63;
    int tb = grp >> 6;
    int iwt = n >> 4, iwh = (n >> 2) & 3, iww = n & 3;
    int ipt = s >> 6, iph = (s >> 3) & 7, ipw = s & 7;
    int lt = iwt*2 + ipt;
    int lh = iwh*8 + iph;
    int lw = iww*8 + ipw;
    return (((tb*8 + lt)*32 + lh)*32 + lw) * C_;
}

__device__ __forceinline__ uint32_t smem_to_u32(const void* p) {
    uint32_t a;
    asm("{ .reg .u64 t; cvta.to.shared.u64 t, %1; cvt.u32.u64 %0, t; }" : "=r"(a) : "l"(p));
    return a;
}
__device__ __forceinline__ void cp16(uint32_t dst, const void* src) {
    asm volatile("cp.async.cg.shared.global [%0], [%1], 16;" :: "r"(dst), "l"(src));
}
__device__ __forceinline__ void mma16816(float* c, const uint32_t* a, const uint32_t* b) {
    asm volatile(
        "mma.sync.aligned.m16n8k16.row.col.f32.f16.f16.f32 "
        "{%0,%1,%2,%3}, {%4,%5,%6,%7}, {%8,%9}, {%0,%1,%2,%3};"
        : "+f"(c[0]), "+f"(c[1]), "+f"(c[2]), "+f"(c[3])
        : "r"(a[0]), "r"(a[1]), "r"(a[2]), "r"(a[3]), "r"(b[0]), "r"(b[1]));
}

// fp32 sequential-fma recompute in reference-matching order; coalesced W.
__device__ float refine_dot(const float* __restrict__ x, int by, int s, int col) {
    const float* xr = x + x_row_off(by, s);
    const float* wc = g_Wqt + (size_t)col * 256;
    float acc = 0.f;
    for (int k = 0; k < 256; k++)
        acc = fmaf(xr[k], wc[k], acc);
    return acc;
}

// ---------------- K1: fused windowize-gather(fp16) + region partials ----------------
__global__ void gather_region_kernel(const float* __restrict__ x) {
    int bn = blockIdx.x, ch = blockIdx.y, c = threadIdx.x;
    int b = bn >> 6, n = bn & 63;
    float acc = 0.f;
    #pragma unroll 4
    for (int l = 0; l < 64; l++) {
        int p = ch*64 + l;
        int t = p >> 7, s = p & 127;
        int grp = (t*B_ + b)*NW + n;
        float v = x[x_row_off(grp, s) + c];
        acc += v;
        g_xh[(size_t)(grp*WS + s)*C_ + c] = __float2half_rn(v);
    }
    g_rpart[(bn*8 + ch)*C_ + c] = acc;
}

// ---------------- K2: W transpose + fp16 cast ----------------
__global__ void wtrans_kernel(const float* __restrict__ Wqkv,
                              const float* __restrict__ Wproj) {
    int idx = blockIdx.x*256 + threadIdx.x;
    if (idx < 256*768) {
        int k = idx / 768, n = idx % 768;
        float v = Wqkv[idx];
        g_Wq_h[n*256 + k] = __float2half_rn(v);
        g_Wqt[(size_t)n*256 + k] = v;
    }
    if (idx < 256*256) {
        int k = idx / 256, n = idx % 256;
        g_Wp_h[n*256 + k] = __float2half_rn(Wproj[idx]);
    }
}

// ---------------- K3: region final reduce ----------------
__global__ void region_b_kernel() {
    int bn = blockIdx.x, c = threadIdx.x;
    float acc = 0.f;
    #pragma unroll
    for (int ch = 0; ch < 8; ch++) acc += g_rpart[(bn*8 + ch)*C_ + c];
    g_region[bn*C_ + c] = acc * (1.0f / WS);
}

// ---------------- K5: routing top-4 (parallel dots) ----------------
__global__ void route_kernel() {
    int bi = blockIdx.x;
    int b  = bi >> 6;
    __shared__ float sI[C_];
    __shared__ float sc[NW];
    sI[threadIdx.x] = g_region[bi*C_ + threadIdx.x];   // 256 threads
    __syncthreads();
    int j = threadIdx.x >> 2, q = threadIdx.x & 3;
    const float* rj = &g_region[(b*NW + j)*C_];
    float d = 0.f;
    #pragma unroll 8
    for (int c = q*64; c < q*64 + 64; c++) d += sI[c] * rj[c];
    d += __shfl_xor_sync(0xffffffffu, d, 1);
    d += __shfl_xor_sync(0xffffffffu, d, 2);
    if (q == 0) sc[j] = d;
    __syncthreads();
    if (threadIdx.x == 0) {
        unsigned long long taken = 0ull;
        for (int r = 0; r < TOPK; r++) {
            float best = -1e30f; int bj = 0;
            for (int jj = 0; jj < NW; jj++)
                if (!((taken >> jj) & 1ull) && sc[jj] > best) { best = sc[jj]; bj = jj; }
            taken |= 1ull << bj;
            g_idx[bi*TOPK + r] = bj;
        }
    }
}

// ---------------- K4/K8: 1-pass fp16 GEMM via mma.sync ----------------
// CTA tile 128x128, 8 warps (2x4, warp 64x32), BK=32 (8 iterations),
// XOR-swizzled 64B rows, 3-stage cp.async, 2 CTAs/SM.
// Chunk body batches ALL B-LDSM (both k16 steps) up front for MLP.
// MODE 0: A = g_xh, B = Wqkv (N=768), epi = LIF + margin-refine + bitpack
// MODE 1: A = g_ah, B = Wproj (N=256), epi = bias + un-windowize
#define A_PANE  8192               // 128 rows * 64 B
#define STB     16384              // A + B per stage
#define NSTAGE  3                  // 48 KB total (static smem cap)
#define SWZ(row, p) (((p) ^ (((row) >> 1) & 3)) * 16)

template<int MODE>
__global__ void __launch_bounds__(256, 2)
gemm_mma_kernel(const float* __restrict__ bias_g, float* __restrict__ out,
                const float* __restrict__ x_full) {
    __shared__ __align__(16) char smem[NSTAGE*STB];    // 49152 = 48 KB
    uint32_t sb = smem_to_u32(smem);
    int tid = threadIdx.x, lane = tid & 31, wid = tid >> 5;
    int warp_m = wid & 1, warp_n = wid >> 1;           // 2 x 4 (warp 64x32)
    int bx = blockIdx.x, by = blockIdx.y;

    const __half* Ah = (MODE == 0) ? g_xh : g_ah;
    const __half* Bh = (MODE == 0) ? g_Wq_h : g_Wp_h;
    size_t arow0 = (size_t)by * 128 * 256;
    size_t brow0 = (size_t)bx * 128 * 256;

    float bv[4][2];
    #pragma unroll
    for (int ni = 0; ni < 4; ni++) {
        int col = bx*128 + warp_n*32 + ni*8 + 2*(lane & 3);
        bv[ni][0] = bias_g[col];
        bv[ni][1] = bias_g[col + 1];
    }

    // loads: per stage, each thread does 2 A + 2 B 16B chunks
    auto stage_load = [&](int c, int s) {
        uint32_t base = sb + s*STB;
        #pragma unroll
        for (int i = 0; i < 2; i++) {
            int idx = i*256 + tid;              // 0..511
            int row = idx >> 2, p = idx & 3;    // row 0..127, 16B part 0..3
            uint32_t doff = row*64 + SWZ(row, p);
            cp16(base + doff,          Ah + arow0 + (size_t)row*256 + c*32 + p*8);
            cp16(base + A_PANE + doff, Bh + brow0 + (size_t)row*256 + c*32 + p*8);
        }
        asm volatile("cp.async.commit_group;" ::: "memory");
    };

    float c[4][4][4];
    #pragma unroll
    for (int i = 0; i < 4; i++)
        #pragma unroll
        for (int j = 0; j < 4; j++)
            #pragma unroll
            for (int k = 0; k < 4; k++) c[i][j][k] = 0.f;

    stage_load(0, 0);
    stage_load(1, 1);
    int sc_ = 0;
    for (int ch = 0; ch < 8; ch++) {       // 8 chunks of K=32
        if (ch < 7) {
            asm volatile("cp.async.wait_group 1;" ::: "memory");
        } else {
            asm volatile("cp.async.wait_group 0;" ::: "memory");
        }
        __syncthreads();
        if (ch < 6) {
            int s2 = sc_ + 2; if (s2 >= NSTAGE) s2 -= NSTAGE;
            stage_load(ch + 2, s2);
        }
        uint32_t stb = sb + sc_*STB;

        // batch ALL B fragments for both k16 steps (8 LDSM in flight)
        uint32_t bh[2][4][2];
        #pragma unroll
        for (int ks = 0; ks < 2; ks++) {
            #pragma unroll
            for (int ni = 0; ni < 4; ni++) {
                int n = warp_n*32 + ni*8 + (lane & 7);
                int p = 2*ks + ((lane >> 3) & 1);
                asm volatile("ldmatrix.sync.aligned.m8n8.x2.shared.b16 {%0,%1}, [%2];"
                    : "=r"(bh[ks][ni][0]), "=r"(bh[ks][ni][1])
                    : "r"(stb + A_PANE + n*64 + SWZ(n, p)));
            }
        }
        #pragma unroll
        for (int mi = 0; mi < 4; mi++) {
            int m = warp_m*64 + mi*16 + (lane & 15);
            int p0 = (lane >> 4), p1 = 2 + (lane >> 4);
            uint32_t a0[4], a1[4];
            asm volatile("ldmatrix.sync.aligned.m8n8.x4.shared.b16 {%0,%1,%2,%3}, [%4];"
                : "=r"(a0[0]), "=r"(a0[1]), "=r"(a0[2]), "=r"(a0[3])
                : "r"(stb + m*64 + SWZ(m, p0)));
            asm volatile("ldmatrix.sync.aligned.m8n8.x4.shared.b16 {%0,%1,%2,%3}, [%4];"
                : "=r"(a1[0]), "=r"(a1[1]), "=r"(a1[2]), "=r"(a1[3])
                : "r"(stb + m*64 + SWZ(m, p1)));
            #pragma unroll
            for (int ni = 0; ni < 4; ni++)
                mma16816(c[mi][ni], a0, bh[0][ni]);
            #pragma unroll
            for (int ni = 0; ni < 4; ni++)
                mma16816(c[mi][ni], a1, bh[1][ni]);
        }
        if (++sc_ >= NSTAGE) sc_ = 0;
    }

    // ---------------- epilogue ----------------
    if (MODE == 0) {
        #pragma unroll
        for (int mi = 0; mi < 4; mi++) {
            #pragma unroll
            for (int half = 0; half < 2; half++) {
                int s = warp_m*64 + mi*16 + half*8 + (lane >> 2);
                unsigned w = 0;
                #pragma unroll
                for (int ni = 0; ni < 4; ni++) {
                    int col = bx*128 + warp_n*32 + ni*8 + 2*(lane & 3);
                    float v0 = c[mi][ni][half*2 + 0] + bv[ni][0];
                    float v1 = c[mi][ni][half*2 + 1] + bv[ni][1];
                    if (fabsf(v0 - 2.0f) < MARGIN0)
                        v0 = refine_dot(x_full, by, s, col) + bv[ni][0];
                    if (fabsf(v1 - 2.0f) < MARGIN0)
                        v1 = refine_dot(x_full, by, s, col + 1) + bv[ni][1];
                    int sh = ni*8 + 2*(lane & 3);
                    w |= (v0 >= 2.0f ? 1u : 0u) << sh;
                    w |= (v1 >= 2.0f ? 1u : 0u) << (sh + 1);
                }
                w |= __shfl_xor_sync(0xffffffffu, w, 1);
                w |= __shfl_xor_sync(0xffffffffu, w, 2);
                if ((lane & 3) == 0) {
                    int wcol = bx*4 + warp_n;          // 0..23
                    unsigned* dst = (wcol < 8) ? g_qb : ((wcol < 16) ? g_kb : g_vb);
                    dst[(by*H_ + (wcol & 7))*WS + s] = w;
                }
            }
        }
    } else {
        #pragma unroll
        for (int mi = 0; mi < 4; mi++) {
            #pragma unroll
            for (int half = 0; half < 2; half++) {
                int s = warp_m*64 + mi*16 + half*8 + (lane >> 2);
                int xo = x_row_off(by, s) + bx*128 + warp_n*32;
                #pragma unroll
                for (int ni = 0; ni < 4; ni++) {
                    float2 o;
                    o.x = c[mi][ni][half*2 + 0] + bv[ni][0];
                    o.y = c[mi][ni][half*2 + 1] + bv[ni][1];
                    *(float2*)&out[xo + ni*8 + 2*(lane & 3)] = o;
                }
            }
        }
    }
}

// ---------------- K6: per-window bit transpose ----------------
__global__ void transpose_kernel() {
    int grp = blockIdx.x;
    int wid = threadIdx.x >> 5, lane = threadIdx.x & 31;
    int base = (grp*H_ + wid);
    #pragma unroll
    for (int cc = 0; cc < 4; cc++) {
        unsigned kw = g_kb[base*WS + cc*32 + lane];
        unsigned vw = g_vb[base*WS + cc*32 + lane];
        unsigned kt = 0, vt = 0;
        #pragma unroll
        for (int d = 0; d < 32; d++) {
            unsigned mk = __ballot_sync(0xffffffffu, (kw >> d) & 1u);
            unsigned mv = __ballot_sync(0xffffffffu, (vw >> d) & 1u);
            if (lane == d) { kt = mk; vt = mv; }
        }
        g_kt[(base*4 + cc)*32 + lane] = kt;
        g_vt[(base*4 + cc)*32 + lane] = vt;
    }
}

// ---------------- K7: popcount linear attention, sparse-q output ----------------
__global__ void __launch_bounds__(256) attn_kernel() {
    int grp = blockIdx.x;
    int n = grp & 63, tb = grp >> 6, b = tb % B_;
    int wid = threadIdx.x >> 5, lane = threadIdx.x & 31;
    int h = wid;
    __shared__ int s_idx[TOPK];
    __shared__ int s_ks[H_][32];
    __shared__ int s_kv[H_][32][32];   // [h][d][e]
    if (threadIdx.x < TOPK)
        s_idx[threadIdx.x] = g_idx[(b*NW + n)*TOPK + threadIdx.x];
    __syncthreads();

    unsigned kv[32];
    #pragma unroll
    for (int d = 0; d < 32; d++) kv[d] = 0;
    unsigned ksum = 0;

    for (int j = 0; j < TOPK; j++) {
        int gsrc = tb*NW + s_idx[j];
        const unsigned* ktp = &g_kt[(gsrc*H_ + h)*4*32];
        const unsigned* vtp = &g_vt[(gsrc*H_ + h)*4*32];
        #pragma unroll
        for (int cc = 0; cc < 4; cc++) {
            unsigned ktw = ktp[cc*32 + lane];
            unsigned vtw = vtp[cc*32 + lane];
            ksum += __popc(ktw);
            #pragma unroll
            for (int d = 0; d < 32; d++) {
                unsigned km = __shfl_sync(0xffffffffu, ktw, d);
                kv[d] += __popc(km & vtw);
            }
        }
    }
    #pragma unroll
    for (int d = 0; d < 32; d++) s_kv[h][d][lane] = (int)kv[d];
    s_ks[h][lane] = (int)ksum;
    __syncwarp();

    const int* kvh = &s_kv[h][0][0];
    const int* ksh = &s_ks[h][0];
    const unsigned* qp = &g_qb[(grp*H_ + h)*WS];
    for (int cc = 0; cc < 4; cc++) {
        unsigned qwl = qp[cc*32 + lane];
        #pragma unroll 4
        for (int i = 0; i < 32; i++) {
            unsigned qw = __shfl_sync(0xffffffffu, qwl, i);
            float o = 0.f;
            if (qw) {                          // uniform branch
                int acc = 0, Dv = 0;
                unsigned m = qw;
                do {
                    int d = __ffs(m) - 1;
                    m &= m - 1;
                    acc += kvh[d*32 + lane];
                    Dv  += ksh[d];
                } while (m);
                o = (float)acc / ((float)Dv + 1e-6f);
            }
            size_t off = ((size_t)(grp*WS + cc*32 + i))*C_ + h*32 + lane;
            g_ah[off] = __float2half_rn(o);
        }
    }
}

// ---------------- launcher ----------------
extern "C" void kernel_launch(void* const* d_in, const int* in_sizes, int n_in,
                              void* d_out, int out_size) {
    const float* x      = (const float*)d_in[0];
    const float* W_qkv  = (const float*)d_in[1];
    const float* b_qkv  = (const float*)d_in[2];
    const float* W_proj = (const float*)d_in[3];
    const float* b_proj = (const float*)d_in[4];
    float* out = (float*)d_out;

    gather_region_kernel<<<dim3(128, 8), 256>>>(x);   // 1
    wtrans_kernel<<<768, 256>>>(W_qkv, W_proj);       // 2
    region_b_kernel<<<128, 256>>>();                  // 3
    gemm_mma_kernel<0><<<dim3(6, NGRP), 256>>>(b_qkv, nullptr, x);  // 4 <- ncu slot
    route_kernel<<<B_*NW, 256>>>();                   // 5
    transpose_kernel<<<NGRP, 256>>>();                // 6
    attn_kernel<<<NGRP, 256>>>();                     // 7
    gemm_mma_kernel<1><<<dim3(2, NGRP), 256>>>(b_proj, out, nullptr);  // 8
}